// round 13
// baseline (speedup 1.0000x reference)
#include <cuda_runtime.h>
#include <math.h>

#define NMAX 1024
#define PK 12          // packed floats/gaussian: u,v,halfA,B | halfC,op,r,g | b,zc,pad,pad
#define TW 16
#define TH 8
#define NSEG 3
#define NPIX (TW*TH)   // 128
#define BT (NSEG*NPIX) // 384 threads per block

__device__ float  g_unsorted[NMAX * PK];
__device__ float4 g_bbox_un[NMAX];
__device__ unsigned long long g_ctr = 0;   // monotonic across launches; never reset

// ---------------------------------------------------------------------------
// per-gaussian prep work item (role 0 = geometry, 1..3 = color channel)
// ---------------------------------------------------------------------------
__device__ __forceinline__ void prep_item(int i, int role,
    const float* __restrict__ means, const float* __restrict__ scales,
    const float* __restrict__ quats, const float* __restrict__ fdc,
    const float* __restrict__ frest, const float* __restrict__ opac_in,
    const float* __restrict__ vm, const float* __restrict__ Km)
{
    if (role == 0) {
        const float mx = means[i*3+0], my = means[i*3+1], mz = means[i*3+2];
        const float4 q4 = *(const float4*)&quats[i*4];
        const float sc0 = scales[i*3+0], sc1 = scales[i*3+1], sc2 = scales[i*3+2];
        const float opv = opac_in[i];
        const float R00=vm[0],R01=vm[1],R02=vm[2],t0=vm[3];
        const float R10=vm[4],R11=vm[5],R12=vm[6],t1=vm[7];
        const float R20=vm[8],R21=vm[9],R22=vm[10],t2=vm[11];
        const float fx=Km[0], cx=Km[2], fy=Km[4], cy=Km[5];

        float pcx = R00*mx + R01*my + R02*mz + t0;
        float pcy = R10*mx + R11*my + R12*mz + t1;
        float pcz = R20*mx + R21*my + R22*mz + t2;

        bool  valid = pcz > 0.01f;
        float zc = fmaxf(pcz, 0.01f);

        float qw=q4.x, qx=q4.y, qy=q4.z, qz=q4.w;
        float qn = rsqrtf(qw*qw+qx*qx+qy*qy+qz*qz);
        qw*=qn; qx*=qn; qy*=qn; qz*=qn;
        float G00 = 1.f-2.f*(qy*qy+qz*qz), G01 = 2.f*(qx*qy-qw*qz), G02 = 2.f*(qx*qz+qw*qy);
        float G10 = 2.f*(qx*qy+qw*qz),     G11 = 1.f-2.f*(qx*qx+qz*qz), G12 = 2.f*(qy*qz-qw*qx);
        float G20 = 2.f*(qx*qz-qw*qy),     G21 = 2.f*(qy*qz+qw*qx),     G22 = 1.f-2.f*(qx*qx+qy*qy);

        float s0 = __expf(sc0), s1 = __expf(sc1), s2 = __expf(sc2);

        float M00=G00*s0, M01=G01*s1, M02=G02*s2;
        float M10=G10*s0, M11=G11*s1, M12=G12*s2;
        float M20=G20*s0, M21=G21*s1, M22=G22*s2;

        float V00 = M00*M00 + M01*M01 + M02*M02;
        float V01 = M00*M10 + M01*M11 + M02*M12;
        float V02 = M00*M20 + M01*M21 + M02*M22;
        float V11 = M10*M10 + M11*M11 + M12*M12;
        float V12 = M10*M20 + M11*M21 + M12*M22;
        float V22 = M20*M20 + M21*M21 + M22*M22;

        float T00 = R00*V00 + R01*V01 + R02*V02;
        float T01 = R00*V01 + R01*V11 + R02*V12;
        float T02 = R00*V02 + R01*V12 + R02*V22;
        float T10 = R10*V00 + R11*V01 + R12*V02;
        float T11 = R10*V01 + R11*V11 + R12*V12;
        float T12 = R10*V02 + R11*V12 + R12*V22;
        float T20 = R20*V00 + R21*V01 + R22*V02;
        float T21 = R20*V01 + R21*V11 + R22*V12;
        float T22 = R20*V02 + R21*V12 + R22*V22;

        float C00 = T00*R00 + T01*R01 + T02*R02;
        float C01 = T00*R10 + T01*R11 + T02*R12;
        float C02 = T00*R20 + T01*R21 + T02*R22;
        float C11 = T10*R10 + T11*R11 + T12*R12;
        float C12 = T10*R20 + T11*R21 + T12*R22;
        float C22 = T20*R20 + T21*R21 + T22*R22;

        float iz  = 1.f / zc;
        float iz2 = iz * iz;
        float J00 = fx*iz, J02 = -fx*pcx*iz2;
        float J11 = fy*iz, J12 = -fy*pcy*iz2;

        float w0x = C00*J00 + C02*J02;
        float w0z = C02*J00 + C22*J02;
        float w1x = C01*J11 + C02*J12;
        float w1y = C11*J11 + C12*J12;
        float w1z = C12*J11 + C22*J12;

        float a  = J00*w0x + J02*w0z + 0.3f;
        float bb = J00*w1x + J02*w1z;
        float c  = J11*w1y + J12*w1z + 0.3f;

        float det = a*c - bb*bb;
        bool  okdet = det > 0.f;
        float inv = 1.f / (okdet ? det : 1.f);
        float conA =  c * inv;
        float conB = -bb * inv;
        float conC =  a * inv;

        float u = fx*pcx*iz + cx;
        float v = fy*pcy*iz + cy;

        float op = 1.f / (1.f + __expf(-opv));
        float op_eff = (valid && okdet) ? op : 0.f;

        float4 bbox = make_float4(1e30f, -1e30f, 1e30f, -1e30f);
        if (op_eff > 0.f) {
            float smax = __logf(255.f * op_eff);
            if (smax > 0.f) {
                float rx = sqrtf(2.f * smax * a) + 1e-3f;
                float ry = sqrtf(2.f * smax * c) + 1e-3f;
                bbox = make_float4(u - rx, u + rx, v - ry, v + ry);
            }
        }
        if (op_eff == 0.f) { conA = conB = conC = 0.f; }

        float* dst = &g_unsorted[i * PK];
        *(float4*)dst = make_float4(u, v, 0.5f*conA, conB);
        *(float2*)(dst + 4) = make_float2(0.5f*conC, op_eff);
        dst[9] = zc;
        g_bbox_un[i] = bbox;
    } else {
        const int ch = role - 1;
        const float mx = means[i*3+0], my = means[i*3+1], mz = means[i*3+2];
        const float f0 = fdc[i*3 + ch];
        float fr[15];
        #pragma unroll
        for (int k = 0; k < 15; k++)
            fr[k] = frest[i*45 + k*3 + ch];
        const float R00=vm[0],R01=vm[1],R02=vm[2],t0=vm[3];
        const float R10=vm[4],R11=vm[5],R12=vm[6],t1=vm[7];
        const float R20=vm[8],R21=vm[9],R22=vm[10],t2=vm[11];

        float cpx = -(R00*t0 + R10*t1 + R20*t2);
        float cpy = -(R01*t0 + R11*t1 + R21*t2);
        float cpz = -(R02*t0 + R12*t1 + R22*t2);
        float vdx = mx - cpx, vdy = my - cpy, vdz = mz - cpz;
        float vn = rsqrtf(vdx*vdx + vdy*vdy + vdz*vdz);
        vdx*=vn; vdy*=vn; vdz*=vn;

        float xx=vdx*vdx, yy=vdy*vdy, zz=vdz*vdz;
        float sh[16];
        sh[0]  = 0.28209479177387814f;
        sh[1]  = -0.4886025119029199f * vdy;
        sh[2]  =  0.4886025119029199f * vdz;
        sh[3]  = -0.4886025119029199f * vdx;
        sh[4]  =  1.0925484305920792f * vdx*vdy;
        sh[5]  = -1.0925484305920792f * vdy*vdz;
        sh[6]  =  0.31539156525252005f * (2.f*zz - xx - yy);
        sh[7]  = -1.0925484305920792f * vdx*vdz;
        sh[8]  =  0.5462742152960396f * (xx - yy);
        sh[9]  = -0.5900435899266435f * vdy*(3.f*xx - yy);
        sh[10] =  2.890611442640554f  * vdx*vdy*vdz;
        sh[11] = -0.4570457994644658f * vdy*(4.f*zz - xx - yy);
        sh[12] =  0.37317633259011546f* vdz*(2.f*zz - 3.f*xx - 3.f*yy);
        sh[13] = -0.4570457994644658f * vdx*(4.f*zz - xx - yy);
        sh[14] =  1.445305721320277f  * vdz*(xx - yy);
        sh[15] = -0.5900435899266435f * vdx*(xx - 3.f*yy);

        float acc = 0.5f + sh[0] * f0;
        #pragma unroll
        for (int k = 1; k < 16; k++)
            acc = fmaf(sh[k], fr[k-1], acc);

        g_unsorted[i * PK + 6 + ch] = fmaxf(acc, 0.f);
    }
}

// ---------------------------------------------------------------------------
// Fused kernel: prep -> grid ticket sync -> compaction -> sort -> 3-way split-K
// ---------------------------------------------------------------------------
__global__ __launch_bounds__(BT, 3)
void fused_kernel(const float* __restrict__ means,
                  const float* __restrict__ scales,
                  const float* __restrict__ quats,
                  const float* __restrict__ fdc,
                  const float* __restrict__ frest,
                  const float* __restrict__ opac_in,
                  const float* __restrict__ vm,
                  const float* __restrict__ Km,
                  const float* __restrict__ bg,
                  float* __restrict__ out,
                  int N, int NP, int W, int H)
{
    __shared__ float sgMain[NMAX * 8];          // 32 KB
    __shared__ float sgB[NMAX];                 //  4 KB
    __shared__ __align__(16) float skey[NMAX];  //  4 KB
    __shared__ __align__(16) int   sidx[NMAX];  //  4 KB
    __shared__ float sComb[(NSEG-1) * NPIX * 4];//  4 KB (seg 1..2 partials)
    __shared__ int   warpTot[BT/32];
    __shared__ int   sCount;

    const int tid = threadIdx.x;
    const unsigned GRID = gridDim.x;

    // ---- ticket read (must precede our own increment) ----
    unsigned long long ticket = 0;
    if (tid == 0) ticket = *((volatile unsigned long long*)&g_ctr);

    // ---- phase 0: prep (first 4*NP global threads) ----
    const int gtid = blockIdx.x * BT + tid;
    if (gtid < 4 * NP) {
        int role = gtid / NP;
        int i = gtid - role * NP;
        if (i < N) prep_item(i, role, means, scales, quats, fdc, frest, opac_in, vm, Km);
    }
    __threadfence();
    __syncthreads();

    // ---- grid-wide rendezvous ----
    if (tid == 0) {
        atomicAdd(&g_ctr, 1ULL);
        unsigned long long target = (ticket / GRID) * GRID + GRID;
        while (*((volatile unsigned long long*)&g_ctr) < target) { __nanosleep(40); }
    }
    __syncthreads();

    // ---- phase 1: tile compaction (first 256 threads, 4 gaussians each) ----
    const int tilesX = (W + TW - 1) / TW;
    const int tx = (blockIdx.x % tilesX) * TW;
    const int ty = (blockIdx.x / tilesX) * TH;

    const float x0 = tx + 0.5f, x1 = tx + TW - 0.5f;
    const float y0 = ty + 0.5f, y1 = ty + TH - 0.5f;

    const int wid = tid >> 5, lane = tid & 31;

    const int base = tid * 4;
    unsigned mask = 0;
    int hits = 0;
    if (tid < 256) {
        #pragma unroll
        for (int j = 0; j < 4; j++) {
            float4 bb = g_bbox_un[base + j];
            bool h = (bb.y >= x0) & (bb.x <= x1) & (bb.w >= y0) & (bb.z <= y1);
            mask |= (unsigned)h << j;
            hits += (int)h;
        }
    }

    int v = hits;
    #pragma unroll
    for (int d = 1; d < 32; d <<= 1) {
        int n = __shfl_up_sync(0xffffffffu, v, d);
        if (lane >= d) v += n;
    }
    if (lane == 31) warpTot[wid] = v;
    __syncthreads();
    int woff = 0;
    #pragma unroll
    for (int w = 0; w < BT/32; w++) woff += (w < wid) ? warpTot[w] : 0;
    int off = woff + v - hits;
    if (tid == 0) {
        int s = 0;
        #pragma unroll
        for (int w = 0; w < BT/32; w++) s += warpTot[w];
        sCount = s;
    }

    #pragma unroll
    for (int j = 0; j < 4; j++) {
        if (mask & (1u << j)) {
            const float4* src = (const float4*)&g_unsorted[(base + j) * PK];
            float4 a = src[0], b = src[1], cc = src[2];
            float4* dm = (float4*)&sgMain[off * 8];
            dm[0] = a; dm[1] = b;
            sgB[off]  = cc.x;
            skey[off] = cc.y;
            sidx[off] = off;
            off++;
        }
    }
    __syncthreads();
    const int count = sCount;

    // ---- phase 2: per-tile bitonic sort of (key, slot) ----
    int P = 32;
    while (P < count) P <<= 1;
    for (int e = tid + count; e < P; e += BT) { skey[e] = 3.4e38f; sidx[e] = e; }
    __syncthreads();

    if (P <= 256) {
        const bool act = (tid < P);     // P multiple of 32 -> warp-uniform
        float key = act ? skey[tid] : 3.4e38f;
        int   idx = act ? sidx[tid] : tid;
        for (int k = 2; k <= P; k <<= 1) {
            bool up = ((tid & k) == 0);
            for (int j = k >> 1; j >= 32; j >>= 1) {
                if (act) { skey[tid] = key; sidx[tid] = idx; }
                __syncthreads();
                if (act) {
                    int ixj = tid ^ j;
                    float ok = skey[ixj]; int oi = sidx[ixj];
                    bool mg = (key > ok) || (key == ok && idx > oi);
                    bool take = (((tid & j) == 0) == up) ? mg : !mg;
                    if (take) { key = ok; idx = oi; }
                }
                __syncthreads();
            }
            if (act) {
                int j0 = (k >> 1) < 16 ? (k >> 1) : 16;
                for (int j = j0; j >= 1; j >>= 1) {
                    float ok = __shfl_xor_sync(0xffffffffu, key, j);
                    int   oi = __shfl_xor_sync(0xffffffffu, idx, j);
                    bool mg = (key > ok) || (key == ok && idx > oi);
                    bool take = (((tid & j) == 0) == up) ? mg : !mg;
                    if (take) { key = ok; idx = oi; }
                }
            }
        }
        if (act) { skey[tid] = key; sidx[tid] = idx; }
        __syncthreads();
    } else {
        for (int k = 2; k <= P; k <<= 1) {
            for (int j = k >> 1; j > 0; j >>= 1) {
                for (int e = tid; e < P; e += BT) {
                    int ixj = e ^ j;
                    if (ixj > e) {
                        float k1 = skey[e], k2 = skey[ixj];
                        int   i1 = sidx[e], i2 = sidx[ixj];
                        bool up = ((e & k) == 0);
                        bool gt = (k1 > k2) || (k1 == k2 && i1 > i2);
                        if (gt == up) {
                            skey[e] = k2; skey[ixj] = k1;
                            sidx[e] = i2; sidx[ixj] = i1;
                        }
                    }
                }
                __syncthreads();
            }
        }
    }

    // ---- phase 3: 3-way split-K compositing ----
    const int seg = tid >> 7;            // 0,1,2
    const int pix = tid & (NPIX - 1);
    const int px = tx + (pix & (TW - 1));
    const int py = ty + (pix / TW);
    const float fpx = px + 0.5f;
    const float fpy = py + 0.5f;

    int m1 = (count / 3 + 7) & ~7;       if (m1 > count) m1 = count;
    int m2 = (2 * count / 3 + 7) & ~7;   if (m2 > count) m2 = count;
    if (m2 < m1) m2 = m1;
    const int kbeg = (seg == 0) ? 0  : (seg == 1 ? m1 : m2);
    const int kend = (seg == 0) ? m1 : (seg == 1 ? m2 : count);

    float T = 1.f, cr = 0.f, cg = 0.f, cb = 0.f;

    int k = kbeg;
    const int kend8 = kbeg + ((kend - kbeg) & ~7);
    for (; k < kend8; k += 8) {
        int4 i4a = *(const int4*)&sidx[k];
        int4 i4b = *(const int4*)&sidx[k + 4];
        int sl[8] = { i4a.x, i4a.y, i4a.z, i4a.w, i4b.x, i4b.y, i4b.z, i4b.w };

        float al[8], rr[8], gg[8], bl[8];
        #pragma unroll
        for (int j = 0; j < 8; j++) {
            float4 d0 = *(const float4*)&sgMain[sl[j] * 8];
            float4 d1 = *(const float4*)&sgMain[sl[j] * 8 + 4];
            float dx = fpx - d0.x;
            float dy = fpy - d0.y;
            float sigma = fmaf(d0.z * dx, dx, fmaf(d1.x * dy, dy, d0.w * dx * dy));
            float a = fminf(d1.y * __expf(-fmaxf(sigma, 0.f)), 0.999f);
            bool ok = (sigma >= 0.f) & (a >= (1.0f / 255.0f));
            al[j] = ok ? a : 0.f;
            rr[j] = d1.z; gg[j] = d1.w; bl[j] = sgB[sl[j]];
        }
        #pragma unroll
        for (int j = 0; j < 8; j++) {
            float w = T * al[j];
            cr = fmaf(w, rr[j], cr);
            cg = fmaf(w, gg[j], cg);
            cb = fmaf(w, bl[j], cb);
            T -= w;
        }
        if (T < 1e-5f) break;
    }
    if (T >= 1e-5f) {
        for (; k < kend; k++) {
            int sl = sidx[k];
            float4 d0 = *(const float4*)&sgMain[sl * 8];
            float4 d1 = *(const float4*)&sgMain[sl * 8 + 4];
            float dx = fpx - d0.x;
            float dy = fpy - d0.y;
            float sigma = fmaf(d0.z * dx, dx, fmaf(d1.x * dy, dy, d0.w * dx * dy));
            float a = fminf(d1.y * __expf(-fmaxf(sigma, 0.f)), 0.999f);
            bool ok = (sigma >= 0.f) & (a >= (1.0f / 255.0f));
            float w = ok ? T * a : 0.f;
            cr = fmaf(w, d1.z, cr);
            cg = fmaf(w, d1.w, cg);
            cb = fmaf(w, sgB[sl], cb);
            T -= w;
        }
    }

    // segments 1,2 publish partials
    if (seg > 0) {
        float4* dst = (float4*)&sComb[((seg - 1) * NPIX + pix) * 4];
        *dst = make_float4(cr, cg, cb, T);
    }
    __syncthreads();

    // segment 0 combines: C = C0 + T0*(C1 + T1*C2), T = T0*T1*T2
    if (seg == 0 && px < W && py < H) {
        float4 b1 = *(const float4*)&sComb[(0 * NPIX + pix) * 4];
        float4 b2 = *(const float4*)&sComb[(1 * NPIX + pix) * 4];
        float c1r = fmaf(b1.w, b2.x, b1.x);
        float c1g = fmaf(b1.w, b2.y, b1.y);
        float c1b = fmaf(b1.w, b2.z, b1.z);
        float T12 = b1.w * b2.w;
        float r = fmaf(T, c1r, cr);
        float g = fmaf(T, c1g, cg);
        float b = fmaf(T, c1b, cb);
        float Tt = T * T12;
        int p = py * W + px;
        out[p*3 + 0] = fmaf(Tt, bg[0], r);
        out[p*3 + 1] = fmaf(Tt, bg[1], g);
        out[p*3 + 2] = fmaf(Tt, bg[2], b);
    }
}

// ---------------------------------------------------------------------------
extern "C" void kernel_launch(void* const* d_in, const int* in_sizes, int n_in,
                              void* d_out, int out_size)
{
    const float* means  = (const float*)d_in[0];
    const float* scales = (const float*)d_in[1];
    const float* quats  = (const float*)d_in[2];
    const float* fdc    = (const float*)d_in[3];
    const float* frest  = (const float*)d_in[4];
    const float* opac   = (const float*)d_in[5];
    const float* vm     = (const float*)d_in[6];
    const float* Km     = (const float*)d_in[7];
    const float* bg     = (const float*)d_in[8];
    float* out = (float*)d_out;

    int N = in_sizes[0] / 3;
    if (N > NMAX) N = NMAX;

    int total = out_size / 3;
    int W = (int)(sqrt((double)total) + 0.5);
    if (W <= 0) W = 224;
    int H = total / W;

    int NP = (N + 31) & ~31;

    int tilesX = (W + TW - 1) / TW;
    int tilesY = (H + TH - 1) / TH;
    fused_kernel<<<tilesX * tilesY, BT>>>(means, scales, quats, fdc, frest,
                                          opac, vm, Km, bg, out, N, NP, W, H);
}

// round 14
// speedup vs baseline: 1.1604x; 1.1604x over previous
#include <cuda_runtime.h>
#include <math.h>

#define NMAX 1024
#define PK 12          // packed floats/gaussian: u,v,halfA,B | halfC,op,r,g | b,zc,pad,pad
#define TW 16
#define TH 8
#define BT 256         // threads per block: 2 segments x 128 pixels
#define NPIX (TW*TH)   // 128

__device__ float  g_unsorted[NMAX * PK];
__device__ float4 g_bbox_un[NMAX];
__device__ unsigned long long g_ctr = 0;   // monotonic across launches; never reset

// ---------------------------------------------------------------------------
// per-gaussian prep work item (role 0 = geometry, 1..3 = color channel)
// ---------------------------------------------------------------------------
__device__ __forceinline__ void prep_item(int i, int role,
    const float* __restrict__ means, const float* __restrict__ scales,
    const float* __restrict__ quats, const float* __restrict__ fdc,
    const float* __restrict__ frest, const float* __restrict__ opac_in,
    const float* __restrict__ vm, const float* __restrict__ Km)
{
    if (role == 0) {
        const float mx = means[i*3+0], my = means[i*3+1], mz = means[i*3+2];
        const float4 q4 = *(const float4*)&quats[i*4];
        const float sc0 = scales[i*3+0], sc1 = scales[i*3+1], sc2 = scales[i*3+2];
        const float opv = opac_in[i];
        const float R00=vm[0],R01=vm[1],R02=vm[2],t0=vm[3];
        const float R10=vm[4],R11=vm[5],R12=vm[6],t1=vm[7];
        const float R20=vm[8],R21=vm[9],R22=vm[10],t2=vm[11];
        const float fx=Km[0], cx=Km[2], fy=Km[4], cy=Km[5];

        float pcx = R00*mx + R01*my + R02*mz + t0;
        float pcy = R10*mx + R11*my + R12*mz + t1;
        float pcz = R20*mx + R21*my + R22*mz + t2;

        bool  valid = pcz > 0.01f;
        float zc = fmaxf(pcz, 0.01f);

        float qw=q4.x, qx=q4.y, qy=q4.z, qz=q4.w;
        float qn = rsqrtf(qw*qw+qx*qx+qy*qy+qz*qz);
        qw*=qn; qx*=qn; qy*=qn; qz*=qn;
        float G00 = 1.f-2.f*(qy*qy+qz*qz), G01 = 2.f*(qx*qy-qw*qz), G02 = 2.f*(qx*qz+qw*qy);
        float G10 = 2.f*(qx*qy+qw*qz),     G11 = 1.f-2.f*(qx*qx+qz*qz), G12 = 2.f*(qy*qz-qw*qx);
        float G20 = 2.f*(qx*qz-qw*qy),     G21 = 2.f*(qy*qz+qw*qx),     G22 = 1.f-2.f*(qx*qx+qy*qy);

        float s0 = __expf(sc0), s1 = __expf(sc1), s2 = __expf(sc2);

        float M00=G00*s0, M01=G01*s1, M02=G02*s2;
        float M10=G10*s0, M11=G11*s1, M12=G12*s2;
        float M20=G20*s0, M21=G21*s1, M22=G22*s2;

        float V00 = M00*M00 + M01*M01 + M02*M02;
        float V01 = M00*M10 + M01*M11 + M02*M12;
        float V02 = M00*M20 + M01*M21 + M02*M22;
        float V11 = M10*M10 + M11*M11 + M12*M12;
        float V12 = M10*M20 + M11*M21 + M12*M22;
        float V22 = M20*M20 + M21*M21 + M22*M22;

        float T00 = R00*V00 + R01*V01 + R02*V02;
        float T01 = R00*V01 + R01*V11 + R02*V12;
        float T02 = R00*V02 + R01*V12 + R02*V22;
        float T10 = R10*V00 + R11*V01 + R12*V02;
        float T11 = R10*V01 + R11*V11 + R12*V12;
        float T12 = R10*V02 + R11*V12 + R12*V22;
        float T20 = R20*V00 + R21*V01 + R22*V02;
        float T21 = R20*V01 + R21*V11 + R22*V12;
        float T22 = R20*V02 + R21*V12 + R22*V22;

        float C00 = T00*R00 + T01*R01 + T02*R02;
        float C01 = T00*R10 + T01*R11 + T02*R12;
        float C02 = T00*R20 + T01*R21 + T02*R22;
        float C11 = T10*R10 + T11*R11 + T12*R12;
        float C12 = T10*R20 + T11*R21 + T12*R22;
        float C22 = T20*R20 + T21*R21 + T22*R22;

        float iz  = 1.f / zc;
        float iz2 = iz * iz;
        float J00 = fx*iz, J02 = -fx*pcx*iz2;
        float J11 = fy*iz, J12 = -fy*pcy*iz2;

        float w0x = C00*J00 + C02*J02;
        float w0z = C02*J00 + C22*J02;
        float w1x = C01*J11 + C02*J12;
        float w1y = C11*J11 + C12*J12;
        float w1z = C12*J11 + C22*J12;

        float a  = J00*w0x + J02*w0z + 0.3f;
        float bb = J00*w1x + J02*w1z;
        float c  = J11*w1y + J12*w1z + 0.3f;

        float det = a*c - bb*bb;
        bool  okdet = det > 0.f;
        float inv = 1.f / (okdet ? det : 1.f);
        float conA =  c * inv;
        float conB = -bb * inv;
        float conC =  a * inv;

        float u = fx*pcx*iz + cx;
        float v = fy*pcy*iz + cy;

        float op = 1.f / (1.f + __expf(-opv));
        float op_eff = (valid && okdet) ? op : 0.f;

        float4 bbox = make_float4(1e30f, -1e30f, 1e30f, -1e30f);
        if (op_eff > 0.f) {
            float smax = __logf(255.f * op_eff);
            if (smax > 0.f) {
                float rx = sqrtf(2.f * smax * a) + 1e-3f;
                float ry = sqrtf(2.f * smax * c) + 1e-3f;
                bbox = make_float4(u - rx, u + rx, v - ry, v + ry);
            }
        }
        if (op_eff == 0.f) { conA = conB = conC = 0.f; }

        float* dst = &g_unsorted[i * PK];
        *(float4*)dst = make_float4(u, v, 0.5f*conA, conB);
        *(float2*)(dst + 4) = make_float2(0.5f*conC, op_eff);
        dst[9] = zc;
        g_bbox_un[i] = bbox;
    } else {
        const int ch = role - 1;
        const float mx = means[i*3+0], my = means[i*3+1], mz = means[i*3+2];
        const float f0 = fdc[i*3 + ch];
        float fr[15];
        #pragma unroll
        for (int k = 0; k < 15; k++)
            fr[k] = frest[i*45 + k*3 + ch];
        const float R00=vm[0],R01=vm[1],R02=vm[2],t0=vm[3];
        const float R10=vm[4],R11=vm[5],R12=vm[6],t1=vm[7];
        const float R20=vm[8],R21=vm[9],R22=vm[10],t2=vm[11];

        float cpx = -(R00*t0 + R10*t1 + R20*t2);
        float cpy = -(R01*t0 + R11*t1 + R21*t2);
        float cpz = -(R02*t0 + R12*t1 + R22*t2);
        float vdx = mx - cpx, vdy = my - cpy, vdz = mz - cpz;
        float vn = rsqrtf(vdx*vdx + vdy*vdy + vdz*vdz);
        vdx*=vn; vdy*=vn; vdz*=vn;

        float xx=vdx*vdx, yy=vdy*vdy, zz=vdz*vdz;
        float sh[16];
        sh[0]  = 0.28209479177387814f;
        sh[1]  = -0.4886025119029199f * vdy;
        sh[2]  =  0.4886025119029199f * vdz;
        sh[3]  = -0.4886025119029199f * vdx;
        sh[4]  =  1.0925484305920792f * vdx*vdy;
        sh[5]  = -1.0925484305920792f * vdy*vdz;
        sh[6]  =  0.31539156525252005f * (2.f*zz - xx - yy);
        sh[7]  = -1.0925484305920792f * vdx*vdz;
        sh[8]  =  0.5462742152960396f * (xx - yy);
        sh[9]  = -0.5900435899266435f * vdy*(3.f*xx - yy);
        sh[10] =  2.890611442640554f  * vdx*vdy*vdz;
        sh[11] = -0.4570457994644658f * vdy*(4.f*zz - xx - yy);
        sh[12] =  0.37317633259011546f* vdz*(2.f*zz - 3.f*xx - 3.f*yy);
        sh[13] = -0.4570457994644658f * vdx*(4.f*zz - xx - yy);
        sh[14] =  1.445305721320277f  * vdz*(xx - yy);
        sh[15] = -0.5900435899266435f * vdx*(xx - 3.f*yy);

        float acc = 0.5f + sh[0] * f0;
        #pragma unroll
        for (int k = 1; k < 16; k++)
            acc = fmaf(sh[k], fr[k-1], acc);

        g_unsorted[i * PK + 6 + ch] = fmaxf(acc, 0.f);
    }
}

// ---------------------------------------------------------------------------
// Fused kernel: prep -> grid ticket sync -> compaction -> rank sort -> split-K
// ---------------------------------------------------------------------------
__global__ __launch_bounds__(BT, 2)
void fused_kernel(const float* __restrict__ means,
                  const float* __restrict__ scales,
                  const float* __restrict__ quats,
                  const float* __restrict__ fdc,
                  const float* __restrict__ frest,
                  const float* __restrict__ opac_in,
                  const float* __restrict__ vm,
                  const float* __restrict__ Km,
                  const float* __restrict__ bg,
                  float* __restrict__ out,
                  int N, int NP, int W, int H)
{
    __shared__ float sgMain[NMAX * 8];          // 32 KB
    __shared__ float sgB[NMAX];                 //  4 KB
    __shared__ __align__(16) float skey[NMAX + 8]; // keys (+pad)
    __shared__ __align__(16) int   sidx[NMAX];  //  4 KB (rank -> slot)
    __shared__ float sComb[NPIX * 4];           //  2 KB
    __shared__ int   warpTot[8];
    __shared__ int   sCount;

    const int tid = threadIdx.x;
    const unsigned GRID = gridDim.x;

    // ---- ticket read (must precede our own increment) ----
    unsigned long long ticket = 0;
    if (tid == 0) ticket = *((volatile unsigned long long*)&g_ctr);

    // ---- phase 0: prep (first 4*NP global threads) ----
    const int gtid = blockIdx.x * BT + tid;
    if (gtid < 4 * NP) {
        int role = gtid / NP;
        int i = gtid - role * NP;
        if (i < N) prep_item(i, role, means, scales, quats, fdc, frest, opac_in, vm, Km);
    }
    __threadfence();
    __syncthreads();

    // ---- grid-wide rendezvous ----
    if (tid == 0) {
        atomicAdd(&g_ctr, 1ULL);
        unsigned long long target = (ticket / GRID) * GRID + GRID;
        while (*((volatile unsigned long long*)&g_ctr) < target) { __nanosleep(40); }
    }
    __syncthreads();

    // ---- phase 1: tile compaction (4 gaussians per thread) ----
    const int tilesX = (W + TW - 1) / TW;
    const int tx = (blockIdx.x % tilesX) * TW;
    const int ty = (blockIdx.x / tilesX) * TH;

    const float x0 = tx + 0.5f, x1 = tx + TW - 0.5f;
    const float y0 = ty + 0.5f, y1 = ty + TH - 0.5f;

    const int wid = tid >> 5, lane = tid & 31;

    const int base = tid * 4;
    unsigned mask = 0;
    int hits = 0;
    #pragma unroll
    for (int j = 0; j < 4; j++) {
        float4 bb = g_bbox_un[base + j];
        bool h = (bb.y >= x0) & (bb.x <= x1) & (bb.w >= y0) & (bb.z <= y1);
        mask |= (unsigned)h << j;
        hits += (int)h;
    }

    int v = hits;
    #pragma unroll
    for (int d = 1; d < 32; d <<= 1) {
        int n = __shfl_up_sync(0xffffffffu, v, d);
        if (lane >= d) v += n;
    }
    if (lane == 31) warpTot[wid] = v;
    __syncthreads();
    int woff = 0;
    #pragma unroll
    for (int w = 0; w < 8; w++) woff += (w < wid) ? warpTot[w] : 0;
    int off = woff + v - hits;
    if (tid == 0) {
        int s = 0;
        #pragma unroll
        for (int w = 0; w < 8; w++) s += warpTot[w];
        sCount = s;
    }

    #pragma unroll
    for (int j = 0; j < 4; j++) {
        if (mask & (1u << j)) {
            const float4* src = (const float4*)&g_unsorted[(base + j) * PK];
            float4 a = src[0], b = src[1], cc = src[2];
            float4* dm = (float4*)&sgMain[off * 8];
            dm[0] = a; dm[1] = b;
            sgB[off]  = cc.x;
            skey[off] = cc.y;
            off++;
        }
    }
    __syncthreads();
    const int count = sCount;

    // ---- phase 2: rank sort (stable ascending; 2 barriers total) ----
    {
        // pad keys to multiple of 4 with +inf for vectorized reads
        int cpad = (count + 3) & ~3;
        for (int e = tid + count; e < cpad; e += BT) skey[e] = 3.4e38f;
        __syncthreads();

        for (int e = tid; e < count; e += BT) {
            float ke = skey[e];
            int rank = 0;
            int j = 0;
            for (; j + 4 <= cpad; j += 4) {
                float4 k4 = *(const float4*)&skey[j];
                rank += (k4.x < ke) || (k4.x == ke && (j + 0) < e);
                rank += (k4.y < ke) || (k4.y == ke && (j + 1) < e);
                rank += (k4.z < ke) || (k4.z == ke && (j + 2) < e);
                rank += (k4.w < ke) || (k4.w == ke && (j + 3) < e);
            }
            sidx[rank] = e;
        }
        __syncthreads();
    }

    // ---- phase 3: split-K compositing (2 threads per pixel) ----
    const int seg = tid >> 7;            // 0 = front half, 1 = back half
    const int pix = tid & (NPIX - 1);
    const int px = tx + (pix & (TW - 1));
    const int py = ty + (pix / TW);
    const float fpx = px + 0.5f;
    const float fpy = py + 0.5f;

    int mid = (count >> 1) + 7; mid &= ~7;     // 8-aligned split
    if (mid > count) mid = count;
    const int kbeg = seg ? mid : 0;
    const int kend = seg ? count : mid;

    float T = 1.f, cr = 0.f, cg = 0.f, cb = 0.f;

    int k = kbeg;
    const int kend8 = kbeg + ((kend - kbeg) & ~7);
    for (; k < kend8; k += 8) {
        int4 i4a = *(const int4*)&sidx[k];
        int4 i4b = *(const int4*)&sidx[k + 4];
        int sl[8] = { i4a.x, i4a.y, i4a.z, i4a.w, i4b.x, i4b.y, i4b.z, i4b.w };

        float al[8], rr[8], gg[8], bl[8];
        #pragma unroll
        for (int j = 0; j < 8; j++) {
            float4 d0 = *(const float4*)&sgMain[sl[j] * 8];
            float4 d1 = *(const float4*)&sgMain[sl[j] * 8 + 4];
            float dx = fpx - d0.x;
            float dy = fpy - d0.y;
            float sigma = fmaf(d0.z * dx, dx, fmaf(d1.x * dy, dy, d0.w * dx * dy));
            float a = fminf(d1.y * __expf(-fmaxf(sigma, 0.f)), 0.999f);
            bool ok = (sigma >= 0.f) & (a >= (1.0f / 255.0f));
            al[j] = ok ? a : 0.f;
            rr[j] = d1.z; gg[j] = d1.w; bl[j] = sgB[sl[j]];
        }
        #pragma unroll
        for (int j = 0; j < 8; j++) {
            float w = T * al[j];
            cr = fmaf(w, rr[j], cr);
            cg = fmaf(w, gg[j], cg);
            cb = fmaf(w, bl[j], cb);
            T -= w;
        }
        if (T < 1e-5f) break;
    }
    if (T >= 1e-5f) {
        for (; k < kend; k++) {
            int sl = sidx[k];
            float4 d0 = *(const float4*)&sgMain[sl * 8];
            float4 d1 = *(const float4*)&sgMain[sl * 8 + 4];
            float dx = fpx - d0.x;
            float dy = fpy - d0.y;
            float sigma = fmaf(d0.z * dx, dx, fmaf(d1.x * dy, dy, d0.w * dx * dy));
            float a = fminf(d1.y * __expf(-fmaxf(sigma, 0.f)), 0.999f);
            bool ok = (sigma >= 0.f) & (a >= (1.0f / 255.0f));
            float w = ok ? T * a : 0.f;
            cr = fmaf(w, d1.z, cr);
            cg = fmaf(w, d1.w, cg);
            cb = fmaf(w, sgB[sl], cb);
            T -= w;
        }
    }

    // back segment publishes partials
    if (seg == 1) {
        float4* dst = (float4*)&sComb[pix * 4];
        *dst = make_float4(cr, cg, cb, T);
    }
    __syncthreads();

    // front segment combines: C = C_f + T_f * C_b ; T = T_f * T_b
    if (seg == 0 && px < W && py < H) {
        float4 bk = *(const float4*)&sComb[pix * 4];
        float Tt = T * bk.w;
        float r = fmaf(T, bk.x, cr);
        float g = fmaf(T, bk.y, cg);
        float b = fmaf(T, bk.z, cb);
        int p = py * W + px;
        out[p*3 + 0] = fmaf(Tt, bg[0], r);
        out[p*3 + 1] = fmaf(Tt, bg[1], g);
        out[p*3 + 2] = fmaf(Tt, bg[2], b);
    }
}

// ---------------------------------------------------------------------------
extern "C" void kernel_launch(void* const* d_in, const int* in_sizes, int n_in,
                              void* d_out, int out_size)
{
    const float* means  = (const float*)d_in[0];
    const float* scales = (const float*)d_in[1];
    const float* quats  = (const float*)d_in[2];
    const float* fdc    = (const float*)d_in[3];
    const float* frest  = (const float*)d_in[4];
    const float* opac   = (const float*)d_in[5];
    const float* vm     = (const float*)d_in[6];
    const float* Km     = (const float*)d_in[7];
    const float* bg     = (const float*)d_in[8];
    float* out = (float*)d_out;

    int N = in_sizes[0] / 3;
    if (N > NMAX) N = NMAX;

    int total = out_size / 3;
    int W = (int)(sqrt((double)total) + 0.5);
    if (W <= 0) W = 224;
    int H = total / W;

    int NP = (N + 31) & ~31;

    int tilesX = (W + TW - 1) / TW;
    int tilesY = (H + TH - 1) / TH;
    fused_kernel<<<tilesX * tilesY, BT>>>(means, scales, quats, fdc, frest,
                                          opac, vm, Km, bg, out, N, NP, W, H);
}